// round 11
// baseline (speedup 1.0000x reference)
#include <cuda_runtime.h>

#define T_STEPS 512
#define IN_F 5
#define HDIM 7
#define TS 64
#define NTILE (T_STEPS / TS)
#define XROW (TS * IN_F + 12)   // 332 words
#define OROW (TS * 4 + 4)       // 260 words

typedef unsigned long long u64;

__device__ __forceinline__ float tanh_ap(float a) {
    float r; asm("tanh.approx.f32 %0, %1;" : "=f"(r) : "f"(a)); return r;
}
__device__ __forceinline__ u64 pk(float lo, float hi) {
    u64 r; asm("mov.b64 %0, {%1, %2};" : "=l"(r) : "f"(lo), "f"(hi)); return r;
}
__device__ __forceinline__ u64 pk1(float v) { return pk(v, v); }
__device__ __forceinline__ void up(u64 v, float& lo, float& hi) {
    asm("mov.b64 {%0, %1}, %2;" : "=f"(lo), "=f"(hi) : "l"(v));
}
__device__ __forceinline__ u64 f2(u64 a, u64 b, u64 c) {
    u64 d; asm("fma.rn.f32x2 %0, %1, %2, %3;" : "=l"(d) : "l"(a), "l"(b), "l"(c)); return d;
}
__device__ __forceinline__ u64 a2(u64 a, u64 b) {
    u64 d; asm("add.rn.f32x2 %0, %1, %2;" : "=l"(d) : "l"(a), "l"(b)); return d;
}

// 1 warp/CTA; warp = 16 batches x 2 lanes. Lane L owns units {4L..4L+3} as two
// f32x2 pairs (unit 7 dummy). Gate algebra as the 99us kernel: r/z pre-halved,
// n h-side pre-halved, r eliminated. Heads packed: lane L computes heads
// {2L, 2L+1} in one f32x2 dot.
__global__ void __launch_bounds__(32) gru_kernel(
    const float* __restrict__ x,
    const float* __restrict__ W_ih, const float* __restrict__ W_hh,
    const float* __restrict__ b_ih, const float* __restrict__ b_hh,
    const float* __restrict__ W_h0,
    const float* __restrict__ W_m, const float* __restrict__ b_m,
    const float* __restrict__ W_r, const float* __restrict__ b_r,
    float* __restrict__ out, int B)
{
    __shared__ __align__(16) float xs[16 * XROW];
    __shared__ __align__(16) float os[16 * OROW];

    int lane = threadIdx.x;
    int g = lane >> 1;          // batch slot 0..15
    int L = lane & 1;
    int b = blockIdx.x * 16 + g;

    float* out_m = out;
    float* out_r = out + (size_t)B * T_STEPS * 3;
    float* out_h = out + (size_t)B * T_STEPS * 4;

    // ---- packed weights: pair p covers units (4L+2p, 4L+2p+1) ----
    u64 pwhr[2][HDIM], pwhz[2][HDIM], pwhn[2][HDIM];   // h-side, pre-halved
    u64 pwir[2][IN_F], pwiz[2][IN_F], pwin[2][IN_F];   // x-side, r/z pre-halved
    u64 pbr[2], pbz[2], pbxn[2], pbhn[2];
    u64 pwout[HDIM], pob;
    float h[4];
    {
#pragma unroll
        for (int p = 0; p < 2; p++) {
            int u0 = 4 * L + 2 * p, u1 = u0 + 1;
            bool v1 = (u1 < HDIM);   // only false for L=1,p=1 (unit 7)
            int r0 = u0, z0 = HDIM + u0, n0 = 2 * HDIM + u0;
            int r1 = u1, z1 = HDIM + u1, n1 = 2 * HDIM + u1;
#pragma unroll
            for (int k = 0; k < HDIM; k++) {
                pwhr[p][k] = pk(0.5f * W_hh[r0 * HDIM + k], v1 ? 0.5f * W_hh[r1 * HDIM + k] : 0.f);
                pwhz[p][k] = pk(0.5f * W_hh[z0 * HDIM + k], v1 ? 0.5f * W_hh[z1 * HDIM + k] : 0.f);
                pwhn[p][k] = pk(0.5f * W_hh[n0 * HDIM + k], v1 ? 0.5f * W_hh[n1 * HDIM + k] : 0.f);
            }
#pragma unroll
            for (int i = 0; i < IN_F; i++) {
                pwir[p][i] = pk(0.5f * W_ih[r0 * IN_F + i], v1 ? 0.5f * W_ih[r1 * IN_F + i] : 0.f);
                pwiz[p][i] = pk(0.5f * W_ih[z0 * IN_F + i], v1 ? 0.5f * W_ih[z1 * IN_F + i] : 0.f);
                pwin[p][i] = pk(W_ih[n0 * IN_F + i], v1 ? W_ih[n1 * IN_F + i] : 0.f);
            }
            pbr[p]  = pk(0.5f * (b_ih[r0] + b_hh[r0]), v1 ? 0.5f * (b_ih[r1] + b_hh[r1]) : 0.f);
            pbz[p]  = pk(0.5f * (b_ih[z0] + b_hh[z0]), v1 ? 0.5f * (b_ih[z1] + b_hh[z1]) : 0.f);
            pbxn[p] = pk(b_ih[n0], v1 ? b_ih[n1] : 0.f);
            pbhn[p] = pk(0.5f * b_hh[n0], v1 ? 0.5f * b_hh[n1] : 0.f);
            h[2 * p]     = W_h0[u0];
            h[2 * p + 1] = v1 ? W_h0[u1] : 0.f;
        }
        // heads: L=0 -> (m0, m1); L=1 -> (m2, r)
#pragma unroll
        for (int k = 0; k < HDIM; k++) {
            float wa = W_m[(2 * L) * HDIM + k];
            float wb = (L == 0) ? W_m[1 * HDIM + k] : W_r[k];
            pwout[k] = pk(wa, wb);
        }
        pob = pk(b_m[2 * L], (L == 0) ? b_m[1] : b_r[0]);
    }

    const float* xb = x + (size_t)b * T_STEPS * IN_F;
    float* xrow = xs + g * XROW;
    float* orow = os + g * OROW;

    // ---- build hall(0): own 4 + partner via shfl_xor; dummy unit 7 dropped ----
    float hall[HDIM];
    {
        float s0 = __shfl_xor_sync(0xffffffffu, h[0], 1, 2);
        float s1 = __shfl_xor_sync(0xffffffffu, h[1], 1, 2);
        float s2 = __shfl_xor_sync(0xffffffffu, h[2], 1, 2);
        float s3 = __shfl_xor_sync(0xffffffffu, h[3], 1, 2);
        hall[0] = L ? s0 : h[0];
        hall[1] = L ? s1 : h[1];
        hall[2] = L ? s2 : h[2];
        hall[3] = L ? s3 : h[3];
        hall[4] = L ? h[0] : s0;
        hall[5] = L ? h[1] : s1;
        hall[6] = L ? h[2] : s2;
    }

    for (int tile = 0; tile < NTILE; tile++) {
        int t0 = tile * TS;

        // ---- stage x tile: 16 batches x 320 floats = 1280 float4, 40/lane ----
        __syncwarp();
        {
            const float* xg0 = x + ((size_t)blockIdx.x * 16) * T_STEPS * IN_F + t0 * IN_F;
#pragma unroll 8
            for (int j = 0; j < 40; j++) {
                int idx = lane + 32 * j;        // 0..1279
                int r = idx / 80;               // batch row
                int c = idx % 80;               // float4 within row
                float4 v = *(const float4*)(xg0 + (size_t)r * T_STEPS * IN_F + c * 4);
                *(float4*)(xs + r * XROW + c * 4) = v;
            }
        }
        __syncwarp();

        // ---- preamble: packed projection of x[t0]; xvn = x[t0+1] ----
        u64 pxa_r[2], pxa_z[2], pxa_n[2];
        float xvn[IN_F];
        {
#pragma unroll
            for (int p = 0; p < 2; p++) {
                u64 Ar = pbr[p], Az = pbz[p], An = pbxn[p];
#pragma unroll
                for (int i = 0; i < IN_F; i++) {
                    u64 xi = pk1(xrow[i]);
                    Ar = f2(pwir[p][i], xi, Ar);
                    Az = f2(pwiz[p][i], xi, Az);
                    An = f2(pwin[p][i], xi, An);
                }
                pxa_r[p] = Ar; pxa_z[p] = Az; pxa_n[p] = An;
            }
#pragma unroll
            for (int i = 0; i < IN_F; i++) xvn[i] = xrow[IN_F + i];
        }

#pragma unroll 1
        for (int tt = 0; tt < TS; tt++) {
            int t2 = (tt + 2 < TS) ? (tt + 2) : (TS - 1);
            float xv2[IN_F];
#pragma unroll
            for (int i = 0; i < IN_F; i++) xv2[i] = xrow[t2 * IN_F + i];

            // ---- pack hall once; reused by gate dots AND head dot ----
            u64 ph[HDIM];
#pragma unroll
            for (int k = 0; k < HDIM; k++) ph[k] = pk1(hall[k]);

            // ---- head dot (for step t-1's h = hall): packed pair ----
            u64 Hd = pob;
#pragma unroll
            for (int k = 0; k < HDIM; k++) Hd = f2(pwout[k], ph[k], Hd);
            {
                float ha, hb; up(Hd, ha, hb);
                // store heads (2L, 2L+1) for this step's hall == h(t-1);
                // hall here is h(t-1), i.e. output row tt-1... but heads use h(t):
                // we store AFTER update below. (see below)
                (void)ha; (void)hb;
                // NOTE: head store moved after h-update using fresh hall.
            }

            // ---- gate dots over hall (2 accumulators), both pairs ----
            u64 pAr[2], pAz[2], pAn[2], pc[2];
#pragma unroll
            for (int p = 0; p < 2; p++) {
                u64 A0 = pxa_r[p], A1 = 0ULL;
                u64 Z0 = pxa_z[p], Z1 = 0ULL;
                u64 N0 = pbhn[p],  N1 = 0ULL;
#pragma unroll
                for (int k = 0; k < HDIM; k += 2) {
                    A0 = f2(pwhr[p][k], ph[k], A0);
                    Z0 = f2(pwhz[p][k], ph[k], Z0);
                    N0 = f2(pwhn[p][k], ph[k], N0);
                    if (k + 1 < HDIM) {
                        A1 = f2(pwhr[p][k + 1], ph[k + 1], A1);
                        Z1 = f2(pwhz[p][k + 1], ph[k + 1], Z1);
                        N1 = f2(pwhn[p][k + 1], ph[k + 1], N1);
                    }
                }
                pAr[p] = a2(A0, A1);
                pAz[p] = a2(Z0, Z1);
                pAn[p] = a2(N0, N1);
                pc[p]  = a2(pAn[p], pxa_n[p]);
            }

            // ---- gates + h update (r eliminated, z = 0.5 + 0.5 tanh) ----
#pragma unroll
            for (int p = 0; p < 2; p++) {
                float ar0, ar1, az0, az1, an0, an1, c0, c1;
                up(pAr[p], ar0, ar1);
                up(pAz[p], az0, az1);
                up(pAn[p], an0, an1);
                up(pc[p],  c0,  c1);
                float tr0 = tanh_ap(ar0), tr1 = tanh_ap(ar1);
                float tz0 = tanh_ap(az0), tz1 = tanh_ap(az1);
                float n0 = tanh_ap(fmaf(tr0, an0, c0));
                float n1 = tanh_ap(fmaf(tr1, an1, c1));
                float z0 = fmaf(0.5f, tz0, 0.5f);
                float z1 = fmaf(0.5f, tz1, 0.5f);
                h[2 * p]     = fmaf(z0, h[2 * p] - n0, n0);
                h[2 * p + 1] = fmaf(z1, h[2 * p + 1] - n1, n1);
            }

            // ---- gather h(t) ----
            {
                float s0 = __shfl_xor_sync(0xffffffffu, h[0], 1, 2);
                float s1 = __shfl_xor_sync(0xffffffffu, h[1], 1, 2);
                float s2 = __shfl_xor_sync(0xffffffffu, h[2], 1, 2);
                float s3 = __shfl_xor_sync(0xffffffffu, h[3], 1, 2);
                hall[0] = L ? s0 : h[0];
                hall[1] = L ? s1 : h[1];
                hall[2] = L ? s2 : h[2];
                hall[3] = L ? s3 : h[3];
                hall[4] = L ? h[0] : s0;
                hall[5] = L ? h[1] : s1;
                hall[6] = L ? h[2] : s2;
            }

            // ---- heads for step tt from fresh hall: packed dot + STS.64 ----
            {
                u64 H2 = pob;
#pragma unroll
                for (int k = 0; k < HDIM; k++) H2 = f2(pwout[k], pk1(hall[k]), H2);
                float ha, hb; up(H2, ha, hb);
                float2 st; st.x = ha; st.y = hb;
                *(float2*)(orow + tt * 4 + 2 * L) = st;
            }

            // ---- packed projection for step t+1 ----
#pragma unroll
            for (int p = 0; p < 2; p++) {
                u64 Ar = pbr[p], Az = pbz[p], An = pbxn[p];
#pragma unroll
                for (int i = 0; i < IN_F; i++) {
                    u64 xi = pk1(xvn[i]);
                    Ar = f2(pwir[p][i], xi, Ar);
                    Az = f2(pwiz[p][i], xi, Az);
                    An = f2(pwin[p][i], xi, An);
                }
                pxa_r[p] = Ar; pxa_z[p] = Az; pxa_n[p] = An;
            }
#pragma unroll
            for (int i = 0; i < IN_F; i++) xvn[i] = xv2[i];
        }
        __syncwarp();

        // ---- flush out_m tile: 48 float4/batch, 24 per lane ----
        float* omg = out_m + (size_t)b * T_STEPS * 3 + t0 * 3;
#pragma unroll 4
        for (int q = 0; q < 24; q++) {
            int p = (2 * q + L) * 4;
            float4 v;
            v.x = orow[((p + 0) / 3) * 4 + (p + 0) % 3];
            v.y = orow[((p + 1) / 3) * 4 + (p + 1) % 3];
            v.z = orow[((p + 2) / 3) * 4 + (p + 2) % 3];
            v.w = orow[((p + 3) / 3) * 4 + (p + 3) % 3];
            *(float4*)(omg + p) = v;
        }
        // ---- flush out_r tile: 16 float4/batch, 8 per lane ----
        float* org = out_r + (size_t)b * T_STEPS + t0;
#pragma unroll 4
        for (int q = 0; q < 8; q++) {
            int p = (2 * q + L) * 4;
            float4 v;
            v.x = orow[(p + 0) * 4 + 3];
            v.y = orow[(p + 1) * 4 + 3];
            v.z = orow[(p + 2) * 4 + 3];
            v.w = orow[(p + 3) * 4 + 3];
            *(float4*)(org + p) = v;
        }
    }

    {
        int nu = L ? 3 : 4;
#pragma unroll
        for (int i = 0; i < 4; i++)
            if (i < nu) out_h[(size_t)b * HDIM + 4 * L + i] = h[i];
    }
}

extern "C" void kernel_launch(void* const* d_in, const int* in_sizes, int n_in,
                              void* d_out, int out_size) {
    const float* x    = (const float*)d_in[0];
    const float* W_ih = (const float*)d_in[2];
    const float* W_hh = (const float*)d_in[3];
    const float* b_ih = (const float*)d_in[4];
    const float* b_hh = (const float*)d_in[5];
    const float* W_h0 = (const float*)d_in[6];
    const float* W_m  = (const float*)d_in[7];
    const float* b_m  = (const float*)d_in[8];
    const float* W_r  = (const float*)d_in[9];
    const float* b_r  = (const float*)d_in[10];

    int B = in_sizes[0] / (T_STEPS * IN_F);   // 8192
    int grid = (B + 15) / 16;                 // 16 batches per 1-warp CTA
    gru_kernel<<<grid, 32>>>(x, W_ih, W_hh, b_ih, b_hh, W_h0,
                             W_m, b_m, W_r, b_r, (float*)d_out, B);
}

// round 13
// speedup vs baseline: 1.8859x; 1.8859x over previous
#include <cuda_runtime.h>

#define T_STEPS 512
#define IN_F 5
#define HDIM 7
#define TS 32
#define NTILE (T_STEPS / TS)    // 16
#define XROW (TS * IN_F + 12)   // 172 words: %32==12 (bank spread), %4==0
#define OROW (TS * 4 + 4)       // 132 words: %32==4,  %4==0

typedef unsigned long long u64;

__device__ __forceinline__ float tanh_ap(float a) {
    float r; asm("tanh.approx.f32 %0, %1;" : "=f"(r) : "f"(a)); return r;
}
__device__ __forceinline__ u64 pk(float lo, float hi) {
    u64 r; asm("mov.b64 %0, {%1, %2};" : "=l"(r) : "f"(lo), "f"(hi)); return r;
}
__device__ __forceinline__ u64 pk1(float v) { return pk(v, v); }
__device__ __forceinline__ void up(u64 v, float& lo, float& hi) {
    asm("mov.b64 {%0, %1}, %2;" : "=f"(lo), "=f"(hi) : "l"(v));
}
__device__ __forceinline__ u64 f2(u64 a, u64 b, u64 c) {
    u64 d; asm("fma.rn.f32x2 %0, %1, %2, %3;" : "=l"(d) : "l"(a), "l"(b), "l"(c)); return d;
}
__device__ __forceinline__ u64 a2(u64 a, u64 b) {
    u64 d; asm("add.rn.f32x2 %0, %1, %2;" : "=l"(d) : "l"(a), "l"(b)); return d;
}

// 4 warps/CTA (wid 0..3 -> even SMSP spread); each warp fully independent:
// 8 batches x 4 lanes, lane L owns units {2L,2L+1} packed lo/hi (unit 7 dummy).
// Gate algebra identical to the 99us champion: r/z pre-halved, n h-side
// pre-halved, r eliminated; dist-2 register prefetch of x; unroll 2.
__global__ void __launch_bounds__(128) gru_kernel(
    const float* __restrict__ x,
    const float* __restrict__ W_ih, const float* __restrict__ W_hh,
    const float* __restrict__ b_ih, const float* __restrict__ b_hh,
    const float* __restrict__ W_h0,
    const float* __restrict__ W_m, const float* __restrict__ b_m,
    const float* __restrict__ W_r, const float* __restrict__ b_r,
    float* __restrict__ out, int B)
{
    __shared__ __align__(16) float xs[32 * XROW];
    __shared__ __align__(16) float os[32 * OROW];

    int lane = threadIdx.x & 31;
    int warp = threadIdx.x >> 5;
    int g = lane >> 2;
    int L = lane & 3;
    int slot = warp * 8 + g;                 // 0..31: batch slot within CTA
    int b = blockIdx.x * 32 + slot;

    float* out_m = out;
    float* out_r = out + (size_t)B * T_STEPS * 3;
    float* out_h = out + (size_t)B * T_STEPS * 4;

    // ---- packed per-lane weights (lo = unit 2L, hi = unit 2L+1) ----
    u64 pwir[IN_F], pwiz[IN_F], pwin[IN_F];   // r,z pre-halved; n unhalved
    u64 pwhr[HDIM], pwhz[HDIM], pwhn[HDIM];   // all h-side pre-halved
    u64 pbr, pbz, pbxn, pbhn;
    float h0s, h1s;
    {
        int u0 = 2 * L, u1 = 2 * L + 1;
        bool v1 = (u1 < HDIM);
        int r0 = u0, z0 = HDIM + u0, n0 = 2 * HDIM + u0;
        int r1 = u1, z1 = HDIM + u1, n1 = 2 * HDIM + u1;
#pragma unroll
        for (int i = 0; i < IN_F; i++) {
            pwir[i] = pk(0.5f * W_ih[r0 * IN_F + i], v1 ? 0.5f * W_ih[r1 * IN_F + i] : 0.f);
            pwiz[i] = pk(0.5f * W_ih[z0 * IN_F + i], v1 ? 0.5f * W_ih[z1 * IN_F + i] : 0.f);
            pwin[i] = pk(W_ih[n0 * IN_F + i], v1 ? W_ih[n1 * IN_F + i] : 0.f);
        }
#pragma unroll
        for (int k = 0; k < HDIM; k++) {
            pwhr[k] = pk(0.5f * W_hh[r0 * HDIM + k], v1 ? 0.5f * W_hh[r1 * HDIM + k] : 0.f);
            pwhz[k] = pk(0.5f * W_hh[z0 * HDIM + k], v1 ? 0.5f * W_hh[z1 * HDIM + k] : 0.f);
            pwhn[k] = pk(0.5f * W_hh[n0 * HDIM + k], v1 ? 0.5f * W_hh[n1 * HDIM + k] : 0.f);
        }
        pbr  = pk(0.5f * (b_ih[r0] + b_hh[r0]), v1 ? 0.5f * (b_ih[r1] + b_hh[r1]) : 0.f);
        pbz  = pk(0.5f * (b_ih[z0] + b_hh[z0]), v1 ? 0.5f * (b_ih[z1] + b_hh[z1]) : 0.f);
        pbxn = pk(b_ih[n0], v1 ? b_ih[n1] : 0.f);
        pbhn = pk(0.5f * b_hh[n0], v1 ? 0.5f * b_hh[n1] : 0.f);
        h0s = W_h0[u0];
        h1s = v1 ? W_h0[u1] : 0.f;
    }
    float wout[HDIM], ob;
#pragma unroll
    for (int k = 0; k < HDIM; k++)
        wout[k] = (L < 3) ? W_m[L * HDIM + k] : W_r[k];
    ob = (L < 3) ? b_m[L] : b_r[0];

    const float* xb = x + (size_t)b * T_STEPS * IN_F;
    float* xrow = xs + slot * XROW;
    float* orow = os + slot * OROW;

    float hall[HDIM];
#pragma unroll
    for (int q = 0; q < 4; q++) {
        hall[2 * q] = __shfl_sync(0xffffffffu, h0s, q, 4);
        if (2 * q + 1 < HDIM)
            hall[2 * q + 1] = __shfl_sync(0xffffffffu, h1s, q, 4);
    }

    for (int tile = 0; tile < NTILE; tile++) {
        int t0 = tile * TS;

        // stage x tile (coalesced float4) — warp-private slice, warp-local sync
        __syncwarp();
        const float4* src = (const float4*)(xb + t0 * IN_F);
#pragma unroll
        for (int j = 0; j < (TS * IN_F) / 16; j++) {   // 10
            float4 v = src[L + 4 * j];
            *(float4*)(xrow + (L + 4 * j) * 4) = v;
        }
        __syncwarp();

        // preamble: packed projection of x[t0]; xvn = x[t0+1]
        u64 pxa_r, pxa_z, pxa_n;
        float xvn[IN_F];
        {
            u64 Ar = pbr, Az = pbz, An = pbxn;
#pragma unroll
            for (int i = 0; i < IN_F; i++) {
                u64 xi = pk1(xrow[i]);
                Ar = f2(pwir[i], xi, Ar);
                Az = f2(pwiz[i], xi, Az);
                An = f2(pwin[i], xi, An);
            }
            pxa_r = Ar; pxa_z = Az; pxa_n = An;
#pragma unroll
            for (int i = 0; i < IN_F; i++) xvn[i] = xrow[IN_F + i];
        }

#pragma unroll 2
        for (int tt = 0; tt < TS; tt++) {
            int t2 = (tt + 2 < TS) ? (tt + 2) : (TS - 1);
            float xv2[IN_F];
#pragma unroll
            for (int i = 0; i < IN_F; i++) xv2[i] = xrow[t2 * IN_F + i];

            // ---- packed gate dot-products over hall (2 accumulators) ----
            u64 ph[HDIM];
#pragma unroll
            for (int k = 0; k < HDIM; k++) ph[k] = pk1(hall[k]);

            u64 Ar0 = pxa_r, Ar1 = 0ULL;
            u64 Az0 = pxa_z, Az1 = 0ULL;
            u64 An0 = pbhn,  An1 = 0ULL;
#pragma unroll
            for (int k = 0; k < HDIM; k += 2) {
                Ar0 = f2(pwhr[k], ph[k], Ar0);
                Az0 = f2(pwhz[k], ph[k], Az0);
                An0 = f2(pwhn[k], ph[k], An0);
                if (k + 1 < HDIM) {
                    Ar1 = f2(pwhr[k + 1], ph[k + 1], Ar1);
                    Az1 = f2(pwhz[k + 1], ph[k + 1], Az1);
                    An1 = f2(pwhn[k + 1], ph[k + 1], An1);
                }
            }
            u64 pAn = a2(An0, An1);        // An' = 0.5*hn (packed)
            u64 pc  = a2(pAn, pxa_n);      // c = xn + An' (packed)

            // ---- gates: r eliminated, z via 0.5+0.5*tanh ----
            float ar0, ar1, az0, az1, an0, an1, c0, c1;
            up(a2(Ar0, Ar1), ar0, ar1);
            up(a2(Az0, Az1), az0, az1);
            up(pAn, an0, an1);
            up(pc, c0, c1);

            float tr0 = tanh_ap(ar0), tr1 = tanh_ap(ar1);
            float tz0 = tanh_ap(az0), tz1 = tanh_ap(az1);
            float n0 = tanh_ap(fmaf(tr0, an0, c0));
            float n1 = tanh_ap(fmaf(tr1, an1, c1));
            float z0 = fmaf(0.5f, tz0, 0.5f);
            float z1 = fmaf(0.5f, tz1, 0.5f);
            h0s = fmaf(z0, h0s - n0, n0);
            h1s = fmaf(z1, h1s - n1, n1);

            // ---- gather h(t) + heads ----
#pragma unroll
            for (int q = 0; q < 4; q++) {
                hall[2 * q] = __shfl_sync(0xffffffffu, h0s, q, 4);
                if (2 * q + 1 < HDIM)
                    hall[2 * q + 1] = __shfl_sync(0xffffffffu, h1s, q, 4);
            }
            float val = ob;
#pragma unroll
            for (int k = 0; k < HDIM; k++) val = fmaf(wout[k], hall[k], val);
            orow[tt * 4 + L] = val;

            // ---- packed projection for step t+1 (off critical path) ----
            {
                u64 Ar = pbr, Az = pbz, An = pbxn;
#pragma unroll
                for (int i = 0; i < IN_F; i++) {
                    u64 xi = pk1(xvn[i]);
                    Ar = f2(pwir[i], xi, Ar);
                    Az = f2(pwiz[i], xi, Az);
                    An = f2(pwin[i], xi, An);
                }
                pxa_r = Ar; pxa_z = Az; pxa_n = An;
            }
#pragma unroll
            for (int i = 0; i < IN_F; i++) xvn[i] = xv2[i];
        }
        __syncwarp();

        // ---- flush out_m tile: TS*3 = 96 floats/batch, 6 float4 per lane ----
        float* omg = out_m + (size_t)b * T_STEPS * 3 + t0 * 3;
#pragma unroll
        for (int q = 0; q < 6; q++) {
            int p = (4 * q + L) * 4;
            float4 v;
            v.x = orow[((p + 0) / 3) * 4 + (p + 0) % 3];
            v.y = orow[((p + 1) / 3) * 4 + (p + 1) % 3];
            v.z = orow[((p + 2) / 3) * 4 + (p + 2) % 3];
            v.w = orow[((p + 3) / 3) * 4 + (p + 3) % 3];
            *(float4*)(omg + p) = v;
        }
        // ---- flush out_r tile: TS = 32 floats/batch, 2 float4 per lane ----
        float* org = out_r + (size_t)b * T_STEPS + t0;
#pragma unroll
        for (int q = 0; q < 2; q++) {
            int p = (4 * q + L) * 4;
            float4 v;
            v.x = orow[(p + 0) * 4 + 3];
            v.y = orow[(p + 1) * 4 + 3];
            v.z = orow[(p + 2) * 4 + 3];
            v.w = orow[(p + 3) * 4 + 3];
            *(float4*)(org + p) = v;
        }
    }

    {
        int u0 = 2 * L, u1 = 2 * L + 1;
        out_h[(size_t)b * HDIM + u0] = h0s;
        if (u1 < HDIM) out_h[(size_t)b * HDIM + u1] = h1s;
    }
}

extern "C" void kernel_launch(void* const* d_in, const int* in_sizes, int n_in,
                              void* d_out, int out_size) {
    const float* x    = (const float*)d_in[0];
    const float* W_ih = (const float*)d_in[2];
    const float* W_hh = (const float*)d_in[3];
    const float* b_ih = (const float*)d_in[4];
    const float* b_hh = (const float*)d_in[5];
    const float* W_h0 = (const float*)d_in[6];
    const float* W_m  = (const float*)d_in[7];
    const float* b_m  = (const float*)d_in[8];
    const float* W_r  = (const float*)d_in[9];
    const float* b_r  = (const float*)d_in[10];

    int B = in_sizes[0] / (T_STEPS * IN_F);   // 8192
    int grid = (B + 31) / 32;                 // 32 batches per 4-warp CTA
    gru_kernel<<<grid, 128>>>(x, W_ih, W_hh, b_ih, b_hh, W_h0,
                              W_m, b_m, W_r, b_r, (float*)d_out, B);
}